// round 2
// baseline (speedup 1.0000x reference)
#include <cuda_runtime.h>
#include <cuda_bf16.h>
#include <mma.h>

using namespace nvcuda;

// Shapes (fixed by problem)
#define BB 32
#define KK 512
#define TT 8
#define DD 256
#define CC 64
#define HH 128
#define WW 128

// ---------------- scratch (static device globals; no cudaMalloc) ----------------
__device__ __align__(16) float g_value[(size_t)BB * HH * WW * DD]; // 512MB, NHWC
__device__ __align__(16) float g_ctx[(size_t)BB * KK * DD];        // 16MB
__device__ __align__(16) float g_wT[9 * CC * DD];                  // [tap][ic][oc]

// ---------------- k0: transpose conv weights to [tap][ic][oc] ----------------
__global__ void k0_wT(const float* __restrict__ conv_w) {
    int idx = blockIdx.x * blockDim.x + threadIdx.x;
    if (idx < 9 * CC * DD) {
        int oc = idx & 255;
        int ic = (idx >> 8) & 63;
        int tap = idx >> 14;
        g_wT[idx] = conv_w[oc * 576 + ic * 9 + tap];
    }
}

// ---------------- k1: 3x3 conv + bias + relu -> g_value (NHWC), tf32 wmma ----------------
// Block: one (b, h) row. Output tile M=128 (w), N=256 (oc). 512 threads = 16 warps (4x4).
// smem: sA [3 rows][130 wi][68 (64 ic + pad)]  (A row-major m x k, k=ic)
//       sB [64 ic][256 oc]                      (B row-major k x n)
//       sBias [256]
// Epilogue staging overlays sA/sB start (16 warps x 2048 floats = 32768 floats,
// strictly below the sBias offset of 42904 floats).
#define SA_LD 68
#define SA_ROW (130 * SA_LD)          // 8840
#define SA_FLOATS (3 * SA_ROW)        // 26520
#define SB_FLOATS (CC * DD)           // 16384
#define CONV_SMEM_FLOATS (SA_FLOATS + SB_FLOATS + 256)
#define CONV_SMEM_BYTES (CONV_SMEM_FLOATS * 4)

__global__ __launch_bounds__(512, 1) void k1_conv(const float* __restrict__ bev,
                                                  const float* __restrict__ conv_b) {
    extern __shared__ float sm[];
    float* sA = sm;
    float* sB = sm + SA_FLOATS;
    float* sBias = sm + SA_FLOATS + SB_FLOATS;

    const int tid = threadIdx.x;
    const int h = blockIdx.x;
    const int b = blockIdx.y;

    if (tid < 256) sBias[tid] = conv_b[tid];

    // Load 3 input rows (with left/right halo) transposed: sA[r][wi][ic]
    for (int r = 0; r < 3; r++) {
        int gh = h - 1 + r;
        bool rowok = (gh >= 0) && (gh < HH);
        for (int idx = tid; idx < CC * 130; idx += 512) {
            int ic = idx / 130;
            int wi = idx - ic * 130;
            int w = wi - 1;
            float v = 0.f;
            if (rowok && (unsigned)w < (unsigned)WW)
                v = bev[(((size_t)b * CC + ic) * HH + gh) * WW + w];
            sA[r * SA_ROW + wi * SA_LD + ic] = v;
        }
    }

    const int warpId = tid >> 5;
    const int m0 = (warpId >> 2) * 32; // 4 warps along M
    const int n0 = (warpId & 3) * 64;  // 4 warps along N

    wmma::fragment<wmma::accumulator, 16, 16, 8, float> cfr[2][4];
#pragma unroll
    for (int i = 0; i < 2; i++)
#pragma unroll
        for (int j = 0; j < 4; j++) wmma::fill_fragment(cfr[i][j], 0.f);

    for (int tap = 0; tap < 9; tap++) {
        __syncthreads(); // previous tap's compute done before overwriting sB
        const float* gw = g_wT + tap * SB_FLOATS;
        for (int idx = tid; idx < SB_FLOATS; idx += 512) sB[idx] = gw[idx];
        __syncthreads();

        const int kh = tap / 3, kw = tap - kh * 3;
        const float* Abase = sA + kh * SA_ROW + kw * SA_LD;

#pragma unroll
        for (int ks = 0; ks < 8; ks++) {
            wmma::fragment<wmma::matrix_a, 16, 16, 8, wmma::precision::tf32, wmma::row_major> afr[2];
            wmma::fragment<wmma::matrix_b, 16, 16, 8, wmma::precision::tf32, wmma::row_major> bfr[4];
#pragma unroll
            for (int i = 0; i < 2; i++) {
                wmma::load_matrix_sync(afr[i], Abase + (m0 + i * 16) * SA_LD + ks * 8, SA_LD);
#pragma unroll
                for (int e = 0; e < afr[i].num_elements; e++)
                    afr[i].x[e] = wmma::__float_to_tf32(afr[i].x[e]);
            }
#pragma unroll
            for (int j = 0; j < 4; j++) {
                wmma::load_matrix_sync(bfr[j], sB + ks * 8 * DD + n0 + j * 16, DD);
#pragma unroll
                for (int e = 0; e < bfr[j].num_elements; e++)
                    bfr[j].x[e] = wmma::__float_to_tf32(bfr[j].x[e]);
            }
#pragma unroll
            for (int i = 0; i < 2; i++)
#pragma unroll
                for (int j = 0; j < 4; j++)
                    wmma::mma_sync(cfr[i][j], afr[i], bfr[j], cfr[i][j]);
        }
    }

    // Epilogue: stage to per-warp smem slice, apply bias+relu, vectorized store NHWC
    __syncthreads();
    float* stage = sm + warpId * 2048; // 32 rows x 64 cols; max 32768 < sBias @ 42904
#pragma unroll
    for (int i = 0; i < 2; i++)
#pragma unroll
        for (int j = 0; j < 4; j++)
            wmma::store_matrix_sync(stage + i * 16 * 64 + j * 16, cfr[i][j], 64,
                                    wmma::mem_row_major);
    __syncwarp();

    const int lane = tid & 31;
    float* gout = g_value + (((size_t)b * HH + h) * WW + m0) * DD + n0;
#pragma unroll
    for (int it = 0; it < 16; it++) {
        int flat = it * 32 + lane;
        int r = flat >> 4;
        int c4 = (flat & 15) * 4;
        float4 v = *(float4*)(stage + r * 64 + c4);
        float4 bb4 = *(float4*)(sBias + n0 + c4);
        v.x = fmaxf(v.x + bb4.x, 0.f);
        v.y = fmaxf(v.y + bb4.y, 0.f);
        v.z = fmaxf(v.z + bb4.z, 0.f);
        v.w = fmaxf(v.w + bb4.w, 0.f);
        *(float4*)(gout + (size_t)r * DD + c4) = v;
    }
}

// ---------------- k2: attention logits + softmax + bilinear gather -> g_ctx ----------------
// One warp per (b,k). 256 threads = 8 warps per block; 2048 blocks.
__global__ __launch_bounds__(256) void k2_sample(const float* __restrict__ queries,
                                                 const float* __restrict__ traj,
                                                 const float* __restrict__ attn_W,
                                                 const float* __restrict__ attn_b) {
    __shared__ float sW[TT * DD];
    __shared__ float sb[TT];
    const int tid = threadIdx.x;
    for (int i = tid; i < TT * DD; i += 256) sW[i] = attn_W[i];
    if (tid < TT) sb[tid] = attn_b[tid];
    __syncthreads();

    const int lane = tid & 31;
    const int g = blockIdx.x * 8 + (tid >> 5); // flattened (b*K + k), 0..16383
    const int b = g >> 9;

    // ---- attention logits ----
    const float* q = queries + (size_t)g * DD;
    float a[TT];
#pragma unroll
    for (int t = 0; t < TT; t++) a[t] = 0.f;
    for (int i = lane; i < DD; i += 32) {
        float qv = q[i];
#pragma unroll
        for (int t = 0; t < TT; t++) a[t] += qv * sW[t * DD + i];
    }
#pragma unroll
    for (int t = 0; t < TT; t++) {
#pragma unroll
        for (int o = 16; o > 0; o >>= 1) a[t] += __shfl_xor_sync(0xffffffffu, a[t], o);
        a[t] += sb[t];
    }
    // softmax (replicated on all lanes, deterministic)
    float mx = a[0];
#pragma unroll
    for (int t = 1; t < TT; t++) mx = fmaxf(mx, a[t]);
    float s = 0.f;
#pragma unroll
    for (int t = 0; t < TT; t++) {
        a[t] = expf(a[t] - mx);
        s += a[t];
    }
    float inv = 1.f / s;
#pragma unroll
    for (int t = 0; t < TT; t++) a[t] *= inv;

    // ---- bilinear gather, weighted accumulate over t & corners ----
    float4 c0 = make_float4(0.f, 0.f, 0.f, 0.f);
    float4 c1 = make_float4(0.f, 0.f, 0.f, 0.f);
    const float* tp = traj + (size_t)g * (TT * 2);
    const float* vbase = g_value + (size_t)b * HH * WW * DD;

#pragma unroll
    for (int t = 0; t < TT; t++) {
        float gy = tp[2 * t] * (1.f / 32.f);     // traj[...,0] -> height coord
        float gx = tp[2 * t + 1] * (1.f / 32.f); // traj[...,1] -> width coord
        float x = (gx + 1.f) * (WW * 0.5f) - 0.5f;
        float y = (gy + 1.f) * (HH * 0.5f) - 0.5f;
        float fx0 = floorf(x), fy0 = floorf(y);
        int x0 = (int)fx0, y0 = (int)fy0;
        float wx1 = x - fx0, wx0 = 1.f - wx1;
        float wy1 = y - fy0, wy0 = 1.f - wy1;
        float at = a[t];

        int xs[4] = {x0, x0 + 1, x0, x0 + 1};
        int ys[4] = {y0, y0, y0 + 1, y0 + 1};
        float ws[4] = {at * wx0 * wy0, at * wx1 * wy0, at * wx0 * wy1, at * wx1 * wy1};
#pragma unroll
        for (int cidx = 0; cidx < 4; cidx++) {
            int xi = xs[cidx], yi = ys[cidx];
            if ((unsigned)xi < (unsigned)WW && (unsigned)yi < (unsigned)HH) {
                float w = ws[cidx];
                const float4* vp = (const float4*)(vbase + ((size_t)yi * WW + xi) * DD);
                float4 v0 = vp[lane];
                float4 v1 = vp[32 + lane];
                c0.x += w * v0.x; c0.y += w * v0.y; c0.z += w * v0.z; c0.w += w * v0.w;
                c1.x += w * v1.x; c1.y += w * v1.y; c1.z += w * v1.z; c1.w += w * v1.w;
            }
        }
    }

    float* co = g_ctx + (size_t)g * DD;
    *(float4*)(co + lane * 4) = c0;
    *(float4*)(co + 128 + lane * 4) = c1;
}

// ---------------- k3: out = ctx @ out_W^T + out_b + queries ----------------
// 256 blocks x 256 threads; block computes 64 rows x 256 oc. Register-blocked:
// thread = (tx=oc/4 group, ty=row/16 group): acc float4[16].
__global__ __launch_bounds__(256) void k3_out(const float* __restrict__ queries,
                                              const float* __restrict__ out_W,
                                              const float* __restrict__ out_b,
                                              float* __restrict__ out) {
    __shared__ float sc[64 * 32];
    __shared__ __align__(16) float sw[32 * 260];
    const int tid = threadIdx.x;
    const int row0 = blockIdx.x * 64;
    const int tx = tid & 63;
    const int ty = tid >> 6;
    const int oc4 = tx * 4;

    float4 acc[16];
#pragma unroll
    for (int r = 0; r < 16; r++) acc[r] = make_float4(0.f, 0.f, 0.f, 0.f);

    for (int kc = 0; kc < 8; kc++) {
        __syncthreads();
        for (int idx = tid; idx < 64 * 32; idx += 256) {
            int r = idx >> 5, kk = idx & 31;
            sc[idx] = g_ctx[(size_t)(row0 + r) * DD + kc * 32 + kk];
        }
        for (int idx = tid; idx < 256 * 32; idx += 256) {
            int oc = idx >> 5, kk = idx & 31;
            sw[kk * 260 + oc] = out_W[(size_t)oc * DD + kc * 32 + kk];
        }
        __syncthreads();

#pragma unroll
        for (int kk = 0; kk < 32; kk++) {
            float4 wv = *(float4*)&sw[kk * 260 + oc4];
#pragma unroll
            for (int r = 0; r < 16; r++) {
                float cv = sc[(ty * 16 + r) * 32 + kk];
                acc[r].x += wv.x * cv;
                acc[r].y += wv.y * cv;
                acc[r].z += wv.z * cv;
                acc[r].w += wv.w * cv;
            }
        }
    }

    float4 bb4 = *(const float4*)&out_b[oc4];
#pragma unroll
    for (int r = 0; r < 16; r++) {
        int rg = row0 + ty * 16 + r;
        float4 qv = *(const float4*)&queries[(size_t)rg * DD + oc4];
        float4 o;
        o.x = acc[r].x + bb4.x + qv.x;
        o.y = acc[r].y + bb4.y + qv.y;
        o.z = acc[r].z + bb4.z + qv.z;
        o.w = acc[r].w + bb4.w + qv.w;
        *(float4*)&out[(size_t)rg * DD + oc4] = o;
    }
}

// ---------------- launch ----------------
extern "C" void kernel_launch(void* const* d_in, const int* in_sizes, int n_in,
                              void* d_out, int out_size) {
    const float* queries = (const float*)d_in[0];
    const float* traj = (const float*)d_in[1];
    const float* bev = (const float*)d_in[2];
    const float* conv_w = (const float*)d_in[3];
    const float* conv_b = (const float*)d_in[4];
    const float* attn_W = (const float*)d_in[5];
    const float* attn_b = (const float*)d_in[6];
    const float* out_W = (const float*)d_in[7];
    const float* out_b = (const float*)d_in[8];
    float* out = (float*)d_out;

    cudaFuncSetAttribute(k1_conv, cudaFuncAttributeMaxDynamicSharedMemorySize,
                         CONV_SMEM_BYTES);

    k0_wT<<<(9 * CC * DD + 255) / 256, 256>>>(conv_w);
    k1_conv<<<dim3(HH, BB), 512, CONV_SMEM_BYTES>>>(bev, conv_b);
    k2_sample<<<(BB * KK) / 8, 256>>>(queries, traj, attn_W, attn_b);
    k3_out<<<(BB * KK) / 64, 256>>>(queries, out_W, out_b, out);
}

// round 4
// speedup vs baseline: 2.7902x; 2.7902x over previous
#include <cuda_runtime.h>
#include <cuda_bf16.h>
#include <mma.h>
#include <cstdint>

using namespace nvcuda;

// Shapes (fixed by problem)
#define BB 32
#define KK 512
#define TT 8
#define DD 256
#define CC 64
#define HH 128
#define WW 128

// ---------------- scratch (static device globals; no cudaMalloc) ----------------
__device__ __align__(16) __nv_bfloat16 g_value[(size_t)BB * HH * WW * DD]; // 256MB NHWC bf16
__device__ __align__(16) float g_ctx[(size_t)BB * KK * DD];                // 16MB
__device__ __align__(16) __nv_bfloat16 g_wT[9 * CC * DD];                  // [tap][ic][oc] bf16

// ---------------- cp.async helpers ----------------
__device__ __forceinline__ void cp_async16(void* smem_dst, const void* gsrc) {
    unsigned int s = (unsigned int)__cvta_generic_to_shared(smem_dst);
    asm volatile("cp.async.cg.shared.global [%0], [%1], 16;\n" ::"r"(s), "l"(gsrc));
}
__device__ __forceinline__ void cp_commit() { asm volatile("cp.async.commit_group;\n"); }
__device__ __forceinline__ void cp_wait1() { asm volatile("cp.async.wait_group 1;\n"); }
__device__ __forceinline__ void cp_wait0() { asm volatile("cp.async.wait_group 0;\n"); }

// ---------------- k0: transpose + convert conv weights to bf16 [tap][ic][oc] ----------------
__global__ void k0_wT(const float* __restrict__ conv_w) {
    int idx = blockIdx.x * blockDim.x + threadIdx.x;
    if (idx < 9 * CC * DD) {
        int oc = idx & 255;
        int ic = (idx >> 8) & 63;
        int tap = idx >> 14;
        g_wT[idx] = __float2bfloat16(conv_w[oc * 576 + ic * 9 + tap]);
    }
}

// ---------------- k1: 3x3 conv + bias + relu -> g_value (NHWC bf16), bf16 wmma ----------------
// Block = one (b, h) row: M=128 (w) x N=256 (oc), K=576 (9 taps x 64 ic).
// 512 threads = 16 warps (4 x 4); warp tile 32x64.
// smem: sA bf16 [3][130][SA_LD=72]  (input rows, halo, ic-major inner)
//       sB bf16 double-buffered [2][64][SB_LD=264]  (per-tap weights, cp.async)
//       sBias f32 [256] at fixed high offset (survives epilogue staging overlay)
#define SA_LD 72
#define SA_ROW (130 * SA_LD)              // 9360 bf16
#define SA_ELEMS (3 * SA_ROW)             // 28080 bf16 = 56160 B
#define SB_LD 264
#define SB_ELEMS (CC * SB_LD)             // 16896 bf16 = 33792 B per buffer
#define SBIAS_OFF_B 131072                // byte offset of bias (beyond 16*8KB staging)
#define CONV_SMEM_BYTES (SBIAS_OFF_B + 256 * 4)

__global__ __launch_bounds__(512, 1) void k1_conv(const float* __restrict__ bev,
                                                  const float* __restrict__ conv_b) {
    extern __shared__ __align__(16) char smraw[];
    __nv_bfloat16* sA = (__nv_bfloat16*)smraw;
    __nv_bfloat16* sB0 = (__nv_bfloat16*)(smraw + 56160);
    __nv_bfloat16* sB1 = (__nv_bfloat16*)(smraw + 56160 + 33792);
    float* sBias = (float*)(smraw + SBIAS_OFF_B);

    const int tid = threadIdx.x;
    const int h = blockIdx.x;
    const int b = blockIdx.y;

    if (tid < 256) sBias[tid] = conv_b[tid];

    // ---- async preload tap 0 weights into buffer 0 ----
    {
        const __nv_bfloat16* src = g_wT;
#pragma unroll
        for (int i = 0; i < 4; i++) {
            int c = tid + i * 512;      // 2048 chunks of 8 bf16 (16B)
            int ic = c >> 5, j = c & 31;
            cp_async16(sB0 + ic * SB_LD + j * 8, src + ic * DD + j * 8);
        }
        cp_commit();
    }

    // ---- load 3 input rows (halo'd, transposed to [r][wi][ic]) as bf16 ----
    for (int r = 0; r < 3; r++) {
        int gh = h - 1 + r;
        bool rowok = (gh >= 0) && (gh < HH);
        for (int idx = tid; idx < CC * 130; idx += 512) {
            int ic = idx / 130;
            int wi = idx - ic * 130;
            int w = wi - 1;
            float v = 0.f;
            if (rowok && (unsigned)w < (unsigned)WW)
                v = bev[(((size_t)b * CC + ic) * HH + gh) * WW + w];
            sA[r * SA_ROW + wi * SA_LD + ic] = __float2bfloat16(v);
        }
    }

    const int warpId = tid >> 5;
    const int m0 = (warpId >> 2) * 32; // 4 warps along M
    const int n0 = (warpId & 3) * 64;  // 4 warps along N

    wmma::fragment<wmma::accumulator, 16, 16, 16, float> cfr[2][4];
#pragma unroll
    for (int i = 0; i < 2; i++)
#pragma unroll
        for (int j = 0; j < 4; j++) wmma::fill_fragment(cfr[i][j], 0.f);

    for (int tap = 0; tap < 9; tap++) {
        __nv_bfloat16* sBuf = (tap & 1) ? sB1 : sB0;
        // issue next tap's weights into the other buffer
        if (tap + 1 < 9) {
            __nv_bfloat16* nBuf = (tap & 1) ? sB0 : sB1;
            const __nv_bfloat16* src = g_wT + (tap + 1) * (CC * DD);
#pragma unroll
            for (int i = 0; i < 4; i++) {
                int c = tid + i * 512;
                int ic = c >> 5, j = c & 31;
                cp_async16(nBuf + ic * SB_LD + j * 8, src + ic * DD + j * 8);
            }
            cp_commit();
            cp_wait1(); // current tap's group complete
        } else {
            cp_wait0();
        }
        __syncthreads();

        const int kh = tap / 3, kw = tap - kh * 3;
        const __nv_bfloat16* Abase = sA + kh * SA_ROW + kw * SA_LD;

#pragma unroll
        for (int ks = 0; ks < 4; ks++) { // 64 ic / 16
            wmma::fragment<wmma::matrix_a, 16, 16, 16, __nv_bfloat16, wmma::row_major> afr[2];
            wmma::fragment<wmma::matrix_b, 16, 16, 16, __nv_bfloat16, wmma::row_major> bfr[4];
#pragma unroll
            for (int i = 0; i < 2; i++)
                wmma::load_matrix_sync(afr[i], Abase + (m0 + i * 16) * SA_LD + ks * 16, SA_LD);
#pragma unroll
            for (int j = 0; j < 4; j++)
                wmma::load_matrix_sync(bfr[j], sBuf + (ks * 16) * SB_LD + n0 + j * 16, SB_LD);
#pragma unroll
            for (int i = 0; i < 2; i++)
#pragma unroll
                for (int j = 0; j < 4; j++)
                    wmma::mma_sync(cfr[i][j], afr[i], bfr[j], cfr[i][j]);
        }
        __syncthreads(); // all warps done with sBuf before it is overwritten next+1 iter
    }

    // ---- epilogue: stage fp32, bias+relu, convert bf16, vectorized store NHWC ----
    float* stage = (float*)smraw + warpId * 2048; // 32 rows x 64 cols fp32 per warp
#pragma unroll
    for (int i = 0; i < 2; i++)
#pragma unroll
        for (int j = 0; j < 4; j++)
            wmma::store_matrix_sync(stage + i * 16 * 64 + j * 16, cfr[i][j], 64,
                                    wmma::mem_row_major);
    __syncwarp();

    const int lane = tid & 31;
    __nv_bfloat16* gout = g_value + (((size_t)b * HH + h) * WW + m0) * DD + n0;
#pragma unroll
    for (int it = 0; it < 8; it++) {
        int flat = it * 32 + lane; // 256 chunks of 8 channels
        int r = flat >> 3;
        int c8 = (flat & 7) * 8;
        float4 v0 = *(float4*)(stage + r * 64 + c8);
        float4 v1 = *(float4*)(stage + r * 64 + c8 + 4);
        float4 b0 = *(float4*)(sBias + n0 + c8);
        float4 b1 = *(float4*)(sBias + n0 + c8 + 4);
        v0.x = fmaxf(v0.x + b0.x, 0.f); v0.y = fmaxf(v0.y + b0.y, 0.f);
        v0.z = fmaxf(v0.z + b0.z, 0.f); v0.w = fmaxf(v0.w + b0.w, 0.f);
        v1.x = fmaxf(v1.x + b1.x, 0.f); v1.y = fmaxf(v1.y + b1.y, 0.f);
        v1.z = fmaxf(v1.z + b1.z, 0.f); v1.w = fmaxf(v1.w + b1.w, 0.f);
        uint4 u;
        __nv_bfloat162* hp = (__nv_bfloat162*)&u;
        hp[0] = __floats2bfloat162_rn(v0.x, v0.y);
        hp[1] = __floats2bfloat162_rn(v0.z, v0.w);
        hp[2] = __floats2bfloat162_rn(v1.x, v1.y);
        hp[3] = __floats2bfloat162_rn(v1.z, v1.w);
        *(uint4*)(gout + (size_t)r * DD + c8) = u;
    }
}

// ---------------- k2: attention logits + softmax + bilinear gather -> g_ctx ----------------
// One warp per (b,k). 256 threads = 8 warps per block; 2048 blocks.
// Lane L owns channels [8L, 8L+8): one 16B bf16 load per corner per lane.
__global__ __launch_bounds__(256) void k2_sample(const float* __restrict__ queries,
                                                 const float* __restrict__ traj,
                                                 const float* __restrict__ attn_W,
                                                 const float* __restrict__ attn_b) {
    __shared__ float sW[TT * DD];
    __shared__ float sb[TT];
    const int tid = threadIdx.x;
    for (int i = tid; i < TT * DD; i += 256) sW[i] = attn_W[i];
    if (tid < TT) sb[tid] = attn_b[tid];
    __syncthreads();

    const int lane = tid & 31;
    const int g = blockIdx.x * 8 + (tid >> 5); // flattened (b*K + k)
    const int b = g >> 9;

    // ---- attention logits ----
    const float* q = queries + (size_t)g * DD;
    float a[TT];
#pragma unroll
    for (int t = 0; t < TT; t++) a[t] = 0.f;
    for (int i = lane; i < DD; i += 32) {
        float qv = q[i];
#pragma unroll
        for (int t = 0; t < TT; t++) a[t] += qv * sW[t * DD + i];
    }
#pragma unroll
    for (int t = 0; t < TT; t++) {
#pragma unroll
        for (int o = 16; o > 0; o >>= 1) a[t] += __shfl_xor_sync(0xffffffffu, a[t], o);
        a[t] += sb[t];
    }
    float mx = a[0];
#pragma unroll
    for (int t = 1; t < TT; t++) mx = fmaxf(mx, a[t]);
    float s = 0.f;
#pragma unroll
    for (int t = 0; t < TT; t++) {
        a[t] = expf(a[t] - mx);
        s += a[t];
    }
    float inv = 1.f / s;
#pragma unroll
    for (int t = 0; t < TT; t++) a[t] *= inv;

    // ---- bilinear gather (bf16 value), weighted accumulate over t & corners ----
    float acc[8];
#pragma unroll
    for (int i = 0; i < 8; i++) acc[i] = 0.f;
    const float* tp = traj + (size_t)g * (TT * 2);
    const __nv_bfloat16* vbase = g_value + (size_t)b * HH * WW * DD;

#pragma unroll
    for (int t = 0; t < TT; t++) {
        float gy = tp[2 * t] * (1.f / 32.f);     // traj[...,0] -> height coord
        float gx = tp[2 * t + 1] * (1.f / 32.f); // traj[...,1] -> width coord
        float x = (gx + 1.f) * (WW * 0.5f) - 0.5f;
        float y = (gy + 1.f) * (HH * 0.5f) - 0.5f;
        float fx0 = floorf(x), fy0 = floorf(y);
        int x0 = (int)fx0, y0 = (int)fy0;
        float wx1 = x - fx0, wx0 = 1.f - wx1;
        float wy1 = y - fy0, wy0 = 1.f - wy1;
        float at = a[t];

        int xs[4] = {x0, x0 + 1, x0, x0 + 1};
        int ys[4] = {y0, y0, y0 + 1, y0 + 1};
        float ws[4] = {at * wx0 * wy0, at * wx1 * wy0, at * wx0 * wy1, at * wx1 * wy1};
#pragma unroll
        for (int cidx = 0; cidx < 4; cidx++) {
            int xi = xs[cidx], yi = ys[cidx];
            if ((unsigned)xi < (unsigned)WW && (unsigned)yi < (unsigned)HH) {
                float w = ws[cidx];
                const uint4* vp = (const uint4*)(vbase + ((size_t)yi * WW + xi) * DD);
                uint4 raw = vp[lane];
                const __nv_bfloat162* hp = (const __nv_bfloat162*)&raw;
                float2 f0 = __bfloat1622float2(hp[0]);
                float2 f1 = __bfloat1622float2(hp[1]);
                float2 f2 = __bfloat1622float2(hp[2]);
                float2 f3 = __bfloat1622float2(hp[3]);
                acc[0] += w * f0.x; acc[1] += w * f0.y;
                acc[2] += w * f1.x; acc[3] += w * f1.y;
                acc[4] += w * f2.x; acc[5] += w * f2.y;
                acc[6] += w * f3.x; acc[7] += w * f3.y;
            }
        }
    }

    float* co = g_ctx + (size_t)g * DD + lane * 8;
    *(float4*)co = make_float4(acc[0], acc[1], acc[2], acc[3]);
    *(float4*)(co + 4) = make_float4(acc[4], acc[5], acc[6], acc[7]);
}

// ---------------- k3: out = ctx @ out_W^T + out_b + queries ----------------
// 512 blocks x 256 threads; block computes 32 rows x 256 oc.
// thread = (tx: oc/4, ty: 8-row group); acc float4[8]  (~60 regs -> better occupancy)
__global__ __launch_bounds__(256) void k3_out(const float* __restrict__ queries,
                                              const float* __restrict__ out_W,
                                              const float* __restrict__ out_b,
                                              float* __restrict__ out) {
    __shared__ float sc[32 * 32];
    __shared__ __align__(16) float sw[32 * 260];
    const int tid = threadIdx.x;
    const int row0 = blockIdx.x * 32;
    const int tx = tid & 63;
    const int ty = tid >> 6;
    const int oc4 = tx * 4;

    float4 acc[8];
#pragma unroll
    for (int r = 0; r < 8; r++) acc[r] = make_float4(0.f, 0.f, 0.f, 0.f);

    for (int kc = 0; kc < 8; kc++) {
        __syncthreads();
        for (int idx = tid; idx < 32 * 32; idx += 256) {
            int r = idx >> 5, kk = idx & 31;
            sc[idx] = g_ctx[(size_t)(row0 + r) * DD + kc * 32 + kk];
        }
        for (int idx = tid; idx < 256 * 32; idx += 256) {
            int oc = idx >> 5, kk = idx & 31;
            sw[kk * 260 + oc] = out_W[(size_t)oc * DD + kc * 32 + kk];
        }
        __syncthreads();

#pragma unroll
        for (int kk = 0; kk < 32; kk++) {
            float4 wv = *(float4*)&sw[kk * 260 + oc4];
#pragma unroll
            for (int r = 0; r < 8; r++) {
                float cv = sc[(ty * 8 + r) * 32 + kk];
                acc[r].x += wv.x * cv;
                acc[r].y += wv.y * cv;
                acc[r].z += wv.z * cv;
                acc[r].w += wv.w * cv;
            }
        }
    }

    float4 bb4 = *(const float4*)&out_b[oc4];
#pragma unroll
    for (int r = 0; r < 8; r++) {
        int rg = row0 + ty * 8 + r;
        float4 qv = *(const float4*)&queries[(size_t)rg * DD + oc4];
        float4 o;
        o.x = acc[r].x + bb4.x + qv.x;
        o.y = acc[r].y + bb4.y + qv.y;
        o.z = acc[r].z + bb4.z + qv.z;
        o.w = acc[r].w + bb4.w + qv.w;
        *(float4*)&out[(size_t)rg * DD + oc4] = o;
    }
}

// ---------------- launch ----------------
extern "C" void kernel_launch(void* const* d_in, const int* in_sizes, int n_in,
                              void* d_out, int out_size) {
    const float* queries = (const float*)d_in[0];
    const float* traj = (const float*)d_in[1];
    const float* bev = (const float*)d_in[2];
    const float* conv_w = (const float*)d_in[3];
    const float* conv_b = (const float*)d_in[4];
    const float* attn_W = (const float*)d_in[5];
    const float* attn_b = (const float*)d_in[6];
    const float* out_W = (const float*)d_in[7];
    const float* out_b = (const float*)d_in[8];
    float* out = (float*)d_out;

    cudaFuncSetAttribute(k1_conv, cudaFuncAttributeMaxDynamicSharedMemorySize,
                         CONV_SMEM_BYTES);

    k0_wT<<<(9 * CC * DD + 255) / 256, 256>>>(conv_w);
    k1_conv<<<dim3(HH, BB), 512, CONV_SMEM_BYTES>>>(bev, conv_b);
    k2_sample<<<(BB * KK) / 8, 256>>>(queries, traj, attn_W, attn_b);
    k3_out<<<(BB * KK) / 32, 256>>>(queries, out_W, out_b, out);
}

// round 6
// speedup vs baseline: 2.9297x; 1.0500x over previous
#include <cuda_runtime.h>
#include <cuda_bf16.h>
#include <mma.h>
#include <cstdint>

using namespace nvcuda;

// Shapes (fixed by problem)
#define BB 32
#define KK 512
#define TT 8
#define DD 256
#define CC 64
#define HH 128
#define WW 128

// ---------------- scratch (static device globals; no cudaMalloc) ----------------
__device__ __align__(16) __nv_bfloat16 g_value[(size_t)BB * HH * WW * DD]; // 256MB NHWC bf16
__device__ __align__(16) float g_ctx[(size_t)BB * KK * DD];                // 16MB
__device__ __align__(16) __nv_bfloat16 g_wT[9 * CC * DD];                  // [tap][ic][oc] bf16

// ---------------- cp.async helpers ----------------
__device__ __forceinline__ void cp_async16(void* smem_dst, const void* gsrc) {
    unsigned int s = (unsigned int)__cvta_generic_to_shared(smem_dst);
    asm volatile("cp.async.cg.shared.global [%0], [%1], 16;\n" ::"r"(s), "l"(gsrc));
}
__device__ __forceinline__ void cp_commit() { asm volatile("cp.async.commit_group;\n"); }
__device__ __forceinline__ void cp_wait2() { asm volatile("cp.async.wait_group 2;\n" ::: "memory"); }
__device__ __forceinline__ void cp_wait1() { asm volatile("cp.async.wait_group 1;\n" ::: "memory"); }
__device__ __forceinline__ void cp_wait0() { asm volatile("cp.async.wait_group 0;\n" ::: "memory"); }

// ---------------- k0: transpose + convert conv weights to bf16 [tap][ic][oc] ----------------
__global__ void k0_wT(const float* __restrict__ conv_w) {
    int idx = blockIdx.x * blockDim.x + threadIdx.x;
    if (idx < 9 * CC * DD) {
        int oc = idx & 255;
        int ic = (idx >> 8) & 63;
        int tap = idx >> 14;
        g_wT[idx] = __float2bfloat16(conv_w[oc * 576 + ic * 9 + tap]);
    }
}

// ---------------- k1: 3x3 conv + bias + relu -> g_value (NHWC bf16), bf16 wmma ----------------
// Block = (b, h, oc-half): M=128 (w) x N=128 (oc), K=576 (9 taps x 64 ic).
// 256 threads = 8 warps (4 along M x 2 along N); warp tile 32x64. 2 CTAs/SM.
// smem: sA bf16 [3][130][SA_LD=72]   (input rows, halo, ic inner)      56160 B
//       sB bf16 [3 bufs][64][SB_LD=136] (per-tap weights, cp.async)    3x17408 B
//       sBias f32 [128]                                                512 B
// Epilogue staging (8 warps x 8KB = 64KB fp32) overlays sA+sB0.
#define SA_LD 72
#define SA_ROW (130 * SA_LD)              // 9360 bf16
#define SB_LD 136
#define SB_ELEMS (CC * SB_LD)             // 8704 bf16 = 17408 B
#define SB_OFF_B 56160
#define BIAS_OFF_B (SB_OFF_B + 3 * 17408) // 108384
#define K1_SMEM_BYTES (BIAS_OFF_B + 512)  // 108896

__global__ __launch_bounds__(256, 2) void k1_conv(const float* __restrict__ bev,
                                                  const float* __restrict__ conv_b) {
    extern __shared__ __align__(16) char smraw[];
    __nv_bfloat16* sA = (__nv_bfloat16*)smraw;
    __nv_bfloat16* sB = (__nv_bfloat16*)(smraw + SB_OFF_B);
    float* sBias = (float*)(smraw + BIAS_OFF_B);

    const int tid = threadIdx.x;
    const int h = blockIdx.x;
    const int nh = blockIdx.y;   // oc half: 0 or 1
    const int b = blockIdx.z;

    if (tid < 128) sBias[tid] = conv_b[nh * 128 + tid];

    // ---- async preload taps 0,1 into buffers 0,1 ----
#pragma unroll
    for (int bufi = 0; bufi < 2; bufi++) {
        const __nv_bfloat16* src = g_wT + bufi * (CC * DD) + nh * 128;
        __nv_bfloat16* dst = sB + bufi * SB_ELEMS;
#pragma unroll
        for (int i = 0; i < 4; i++) {
            int c = tid + i * 256;  // 1024 chunks of 8 bf16
            int ic = c >> 4, j = c & 15;
            cp_async16(dst + ic * SB_LD + j * 8, src + ic * DD + j * 8);
        }
        cp_commit();
    }

    // ---- load 3 input rows (halo'd, transposed to [r][wi][ic]) as bf16 ----
    for (int r = 0; r < 3; r++) {
        int gh = h - 1 + r;
        bool rowok = (gh >= 0) && (gh < HH);
        for (int idx = tid; idx < CC * 130; idx += 256) {
            int ic = idx / 130;
            int wi = idx - ic * 130;
            int w = wi - 1;
            float v = 0.f;
            if (rowok && (unsigned)w < (unsigned)WW)
                v = bev[(((size_t)b * CC + ic) * HH + gh) * WW + w];
            sA[r * SA_ROW + wi * SA_LD + ic] = __float2bfloat16(v);
        }
    }

    const int warpId = tid >> 5;
    const int m0 = (warpId >> 1) * 32; // 4 warps along M
    const int n0 = (warpId & 1) * 64;  // 2 warps along N (local within 128)

    wmma::fragment<wmma::accumulator, 16, 16, 16, float> cfr[2][4];
#pragma unroll
    for (int i = 0; i < 2; i++)
#pragma unroll
        for (int j = 0; j < 4; j++) wmma::fill_fragment(cfr[i][j], 0.f);

    for (int tap = 0; tap < 9; tap++) {
        __syncthreads(); // all warps done with tap-1's buffer; prefetch may overwrite buf[(tap+2)%3]

        if (tap + 2 <= 8) { // prefetch tap+2 into buffer used by tap-1
            const __nv_bfloat16* src = g_wT + (tap + 2) * (CC * DD) + nh * 128;
            __nv_bfloat16* dst = sB + ((tap + 2) % 3) * SB_ELEMS;
#pragma unroll
            for (int i = 0; i < 4; i++) {
                int c = tid + i * 256;
                int ic = c >> 4, j = c & 15;
                cp_async16(dst + ic * SB_LD + j * 8, src + ic * DD + j * 8);
            }
            cp_commit();
        }
        // wait for tap's buffer: allowed outstanding groups = 2 (t<7), 1 (t==7), 0 (t==8)
        if (tap < 7) cp_wait2();
        else if (tap == 7) cp_wait1();
        else cp_wait0();

        const int kh = tap / 3, kw = tap - kh * 3;
        const __nv_bfloat16* Abase = sA + kh * SA_ROW + kw * SA_LD;
        const __nv_bfloat16* Bbuf = sB + (tap % 3) * SB_ELEMS;

#pragma unroll
        for (int ks = 0; ks < 4; ks++) { // 64 ic / 16
            wmma::fragment<wmma::matrix_a, 16, 16, 16, __nv_bfloat16, wmma::row_major> afr[2];
            wmma::fragment<wmma::matrix_b, 16, 16, 16, __nv_bfloat16, wmma::row_major> bfr[4];
#pragma unroll
            for (int i = 0; i < 2; i++)
                wmma::load_matrix_sync(afr[i], Abase + (m0 + i * 16) * SA_LD + ks * 16, SA_LD);
#pragma unroll
            for (int j = 0; j < 4; j++)
                wmma::load_matrix_sync(bfr[j], Bbuf + (ks * 16) * SB_LD + n0 + j * 16, SB_LD);
#pragma unroll
            for (int i = 0; i < 2; i++)
#pragma unroll
                for (int j = 0; j < 4; j++)
                    wmma::mma_sync(cfr[i][j], afr[i], bfr[j], cfr[i][j]);
        }
    }

    // ---- epilogue: stage fp32 (overlays sA/sB0), bias+relu, bf16 store ----
    __syncthreads();
    float* stage = (float*)smraw + warpId * 2048; // 32 rows x 64 cols fp32 per warp (64KB total)
#pragma unroll
    for (int i = 0; i < 2; i++)
#pragma unroll
        for (int j = 0; j < 4; j++)
            wmma::store_matrix_sync(stage + i * 16 * 64 + j * 16, cfr[i][j], 64,
                                    wmma::mem_row_major);
    __syncwarp();

    const int lane = tid & 31;
    __nv_bfloat16* gout = g_value + (((size_t)b * HH + h) * WW + m0) * DD + nh * 128 + n0;
#pragma unroll
    for (int it = 0; it < 8; it++) {
        int c = it * 32 + lane;   // 256 chunks of 8 channels (32 rows x 8 chunks)
        int r = c >> 3;
        int c8 = (c & 7) * 8;
        float4 v0 = *(float4*)(stage + r * 64 + c8);
        float4 v1 = *(float4*)(stage + r * 64 + c8 + 4);
        float4 b0 = *(float4*)(sBias + n0 + c8);
        float4 b1 = *(float4*)(sBias + n0 + c8 + 4);
        v0.x = fmaxf(v0.x + b0.x, 0.f); v0.y = fmaxf(v0.y + b0.y, 0.f);
        v0.z = fmaxf(v0.z + b0.z, 0.f); v0.w = fmaxf(v0.w + b0.w, 0.f);
        v1.x = fmaxf(v1.x + b1.x, 0.f); v1.y = fmaxf(v1.y + b1.y, 0.f);
        v1.z = fmaxf(v1.z + b1.z, 0.f); v1.w = fmaxf(v1.w + b1.w, 0.f);
        uint4 u;
        __nv_bfloat162* hp = (__nv_bfloat162*)&u;
        hp[0] = __floats2bfloat162_rn(v0.x, v0.y);
        hp[1] = __floats2bfloat162_rn(v0.z, v0.w);
        hp[2] = __floats2bfloat162_rn(v1.x, v1.y);
        hp[3] = __floats2bfloat162_rn(v1.z, v1.w);
        *(uint4*)(gout + (size_t)r * DD + c8) = u;
    }
}

// ---------------- k2: attention logits + softmax + bilinear gather -> g_ctx ----------------
__global__ __launch_bounds__(256) void k2_sample(const float* __restrict__ queries,
                                                 const float* __restrict__ traj,
                                                 const float* __restrict__ attn_W,
                                                 const float* __restrict__ attn_b) {
    __shared__ float sW[TT * DD];
    __shared__ float sb[TT];
    const int tid = threadIdx.x;
    for (int i = tid; i < TT * DD; i += 256) sW[i] = attn_W[i];
    if (tid < TT) sb[tid] = attn_b[tid];
    __syncthreads();

    const int lane = tid & 31;
    const int g = blockIdx.x * 8 + (tid >> 5);
    const int b = g >> 9;

    const float* q = queries + (size_t)g * DD;
    float a[TT];
#pragma unroll
    for (int t = 0; t < TT; t++) a[t] = 0.f;
    for (int i = lane; i < DD; i += 32) {
        float qv = q[i];
#pragma unroll
        for (int t = 0; t < TT; t++) a[t] += qv * sW[t * DD + i];
    }
#pragma unroll
    for (int t = 0; t < TT; t++) {
#pragma unroll
        for (int o = 16; o > 0; o >>= 1) a[t] += __shfl_xor_sync(0xffffffffu, a[t], o);
        a[t] += sb[t];
    }
    float mx = a[0];
#pragma unroll
    for (int t = 1; t < TT; t++) mx = fmaxf(mx, a[t]);
    float s = 0.f;
#pragma unroll
    for (int t = 0; t < TT; t++) { a[t] = expf(a[t] - mx); s += a[t]; }
    float inv = 1.f / s;
#pragma unroll
    for (int t = 0; t < TT; t++) a[t] *= inv;

    float acc[8];
#pragma unroll
    for (int i = 0; i < 8; i++) acc[i] = 0.f;
    const float* tp = traj + (size_t)g * (TT * 2);
    const __nv_bfloat16* vbase = g_value + (size_t)b * HH * WW * DD;

#pragma unroll
    for (int t = 0; t < TT; t++) {
        float gy = tp[2 * t] * (1.f / 32.f);
        float gx = tp[2 * t + 1] * (1.f / 32.f);
        float x = (gx + 1.f) * (WW * 0.5f) - 0.5f;
        float y = (gy + 1.f) * (HH * 0.5f) - 0.5f;
        float fx0 = floorf(x), fy0 = floorf(y);
        int x0 = (int)fx0, y0 = (int)fy0;
        float wx1 = x - fx0, wx0 = 1.f - wx1;
        float wy1 = y - fy0, wy0 = 1.f - wy1;
        float at = a[t];

        int xs[4] = {x0, x0 + 1, x0, x0 + 1};
        int ys[4] = {y0, y0, y0 + 1, y0 + 1};
        float ws[4] = {at * wx0 * wy0, at * wx1 * wy0, at * wx0 * wy1, at * wx1 * wy1};
#pragma unroll
        for (int cidx = 0; cidx < 4; cidx++) {
            int xi = xs[cidx], yi = ys[cidx];
            if ((unsigned)xi < (unsigned)WW && (unsigned)yi < (unsigned)HH) {
                float w = ws[cidx];
                const uint4* vp = (const uint4*)(vbase + ((size_t)yi * WW + xi) * DD);
                uint4 raw = vp[lane];
                const __nv_bfloat162* hp = (const __nv_bfloat162*)&raw;
                float2 f0 = __bfloat1622float2(hp[0]);
                float2 f1 = __bfloat1622float2(hp[1]);
                float2 f2 = __bfloat1622float2(hp[2]);
                float2 f3 = __bfloat1622float2(hp[3]);
                acc[0] += w * f0.x; acc[1] += w * f0.y;
                acc[2] += w * f1.x; acc[3] += w * f1.y;
                acc[4] += w * f2.x; acc[5] += w * f2.y;
                acc[6] += w * f3.x; acc[7] += w * f3.y;
            }
        }
    }

    float* co = g_ctx + (size_t)g * DD + lane * 8;
    *(float4*)co = make_float4(acc[0], acc[1], acc[2], acc[3]);
    *(float4*)(co + 4) = make_float4(acc[4], acc[5], acc[6], acc[7]);
}

// ---------------- k3: out = ctx @ out_W^T + out_b + queries ----------------
// 1024 blocks x 256 threads; block computes 16 rows x 256 oc; 4 rows/thread (~50 regs)
__global__ __launch_bounds__(256) void k3_out(const float* __restrict__ queries,
                                              const float* __restrict__ out_W,
                                              const float* __restrict__ out_b,
                                              float* __restrict__ out) {
    __shared__ float sc[16 * 32];
    __shared__ __align__(16) float sw[32 * 260];
    const int tid = threadIdx.x;
    const int row0 = blockIdx.x * 16;
    const int tx = tid & 63;
    const int ty = tid >> 6;
    const int oc4 = tx * 4;

    float4 acc[4];
#pragma unroll
    for (int r = 0; r < 4; r++) acc[r] = make_float4(0.f, 0.f, 0.f, 0.f);

    for (int kc = 0; kc < 8; kc++) {
        __syncthreads();
#pragma unroll
        for (int i = 0; i < 2; i++) {
            int idx = tid + i * 256;
            int r = idx >> 5, kk = idx & 31;
            sc[idx] = g_ctx[(size_t)(row0 + r) * DD + kc * 32 + kk];
        }
        for (int idx = tid; idx < 256 * 32; idx += 256) {
            int oc = idx >> 5, kk = idx & 31;
            sw[kk * 260 + oc] = out_W[(size_t)oc * DD + kc * 32 + kk];
        }
        __syncthreads();

#pragma unroll
        for (int kk = 0; kk < 32; kk++) {
            float4 wv = *(float4*)&sw[kk * 260 + oc4];
#pragma unroll
            for (int r = 0; r < 4; r++) {
                float cv = sc[(ty * 4 + r) * 32 + kk];
                acc[r].x += wv.x * cv;
                acc[r].y += wv.y * cv;
                acc[r].z += wv.z * cv;
                acc[r].w += wv.w * cv;
            }
        }
    }

    float4 bb4 = *(const float4*)&out_b[oc4];
#pragma unroll
    for (int r = 0; r < 4; r++) {
        int rg = row0 + ty * 4 + r;
        float4 qv = *(const float4*)&queries[(size_t)rg * DD + oc4];
        float4 o;
        o.x = acc[r].x + bb4.x + qv.x;
        o.y = acc[r].y + bb4.y + qv.y;
        o.z = acc[r].z + bb4.z + qv.z;
        o.w = acc[r].w + bb4.w + qv.w;
        *(float4*)&out[(size_t)rg * DD + oc4] = o;
    }
}

// ---------------- launch ----------------
extern "C" void kernel_launch(void* const* d_in, const int* in_sizes, int n_in,
                              void* d_out, int out_size) {
    const float* queries = (const float*)d_in[0];
    const float* traj = (const float*)d_in[1];
    const float* bev = (const float*)d_in[2];
    const float* conv_w = (const float*)d_in[3];
    const float* conv_b = (const float*)d_in[4];
    const float* attn_W = (const float*)d_in[5];
    const float* attn_b = (const float*)d_in[6];
    const float* out_W = (const float*)d_in[7];
    const float* out_b = (const float*)d_in[8];
    float* out = (float*)d_out;

    cudaFuncSetAttribute(k1_conv, cudaFuncAttributeMaxDynamicSharedMemorySize, K1_SMEM_BYTES);

    k0_wT<<<(9 * CC * DD + 255) / 256, 256>>>(conv_w);
    k1_conv<<<dim3(HH, 2, BB), 256, K1_SMEM_BYTES>>>(bev, conv_b);
    k2_sample<<<(BB * KK) / 8, 256>>>(queries, traj, attn_W, attn_b);
    k3_out<<<(BB * KK) / 16, 256>>>(queries, out_W, out_b, out);
}